// round 14
// baseline (speedup 1.0000x reference)
#include <cuda_runtime.h>
#include <math.h>
#include <stdint.h>

// Problem constants (fixed shapes per reference)
#define N_NODES 100000
#define N_EDGES 1600000
#define F_IN    256
#define F_OUT   128
#define ALPHA   0.2f

typedef unsigned long long ull;

// ---------------- device scratch (static; no allocation allowed) ----------------
__device__ __align__(16) float g_h[(size_t)N_NODES * F_OUT];   // 51.2 MB: h = x @ W
__device__ float g_sl[N_NODES];
__device__ float g_sr[N_NODES];
__device__ int   g_deg[N_NODES];
__device__ int   g_off[N_NODES + 1];
__device__ int   g_cur[N_NODES];
__device__ int   g_src[N_EDGES];
__device__ int   g_is64;

// ---------------- warp reduction helpers ----------------
__device__ __forceinline__ float warpSum(float v) {
#pragma unroll
    for (int o = 16; o > 0; o >>= 1) v += __shfl_xor_sync(0xffffffffu, v, o);
    return v;
}

// packed dual-fp32 FMA (PTX 8.6, sm_100+): acc = a*b + acc, lanewise on 2 floats
#define FMA2(acc, a, b) \
    asm volatile("fma.rn.f32x2 %0, %1, %2, %0;" : "+l"(acc) : "l"(a), "l"(b))

// ---------------- 0) edge dtype detection ----------------
// int64 little-endian with values < 2^31 has zero hi-words at odd int32 slots.
__global__ void detect_kernel(const int* __restrict__ p) {
    int lane = threadIdx.x;
    int bad = 0;
    for (int k = lane; k < 256; k += 32)
        if (p[2 * k + 1] != 0) bad = 1;
    unsigned b = __ballot_sync(0xffffffffu, bad);
    if (lane == 0) g_is64 = (b == 0) ? 1 : 0;
}
__device__ __forceinline__ int edge_at(const void* eidx, long long elem) {
    if (g_is64) return (int)((const long long*)eidx)[elem];
    return ((const int*)eidx)[elem];
}

// ---------------- 1) f32x2 GEMM: h = x @ W (+ fused attention scores) ----------------
// Block tile 64 rows x 128 cols (full F_OUT), 256 threads, each thread 8 rows x 4 cols.
// A staged DUPLICATED as (a,a) float2 -> inner loop is pure LDS64-broadcast + FMA2.
#define KC 32
__global__ __launch_bounds__(256) void gemm_kernel(
    const float* __restrict__ x, const float* __restrict__ w,
    const float* __restrict__ a_l, const float* __restrict__ a_r, int n)
{
    __shared__ __align__(16) float2 As2[64][KC];   // [row][k], value duplicated in .x/.y
    __shared__ __align__(16) float  Bs[KC][F_OUT];

    const int tid = threadIdx.x;
    const int tx  = tid & 31;   // col group: cols tx*4 .. tx*4+3
    const int ty  = tid >> 5;   // row group: rows ty*8 .. ty*8+7
    const int rowBase = blockIdx.x * 64;

    ull acc2[8][2];
#pragma unroll
    for (int i = 0; i < 8; i++) { acc2[i][0] = 0ull; acc2[i][1] = 0ull; }

    for (int k0 = 0; k0 < F_IN; k0 += KC) {
        // A tile: 64 rows x KC floats = 512 float4, 2 per thread, duplicated store
#pragma unroll
        for (int l = 0; l < 2; l++) {
            int idx = tid + l * 256;       // 0..511
            int r   = idx >> 3;            // row 0..63
            int c4  = idx & 7;             // k quad
            float4 v = make_float4(0.f, 0.f, 0.f, 0.f);
            int gr = rowBase + r;
            if (gr < n)
                v = *(const float4*)(x + (size_t)gr * F_IN + k0 + c4 * 4);
            As2[r][c4 * 4 + 0] = make_float2(v.x, v.x);
            As2[r][c4 * 4 + 1] = make_float2(v.y, v.y);
            As2[r][c4 * 4 + 2] = make_float2(v.z, v.z);
            As2[r][c4 * 4 + 3] = make_float2(v.w, v.w);
        }
        // B tile: KC x 128 floats = 1024 float4, 4 per thread
#pragma unroll
        for (int l = 0; l < 4; l++) {
            int idx = tid + l * 256;
            int r   = idx >> 5;            // k row 0..31
            int c4  = idx & 31;            // col quad
            *(float4*)&Bs[r][c4 * 4] =
                *(const float4*)(w + (size_t)(k0 + r) * F_OUT + c4 * 4);
        }
        __syncthreads();

#pragma unroll
        for (int k = 0; k < KC; k++) {
            const ull* bp = (const ull*)&Bs[k][tx * 4];
            ull b0 = bp[0];                // cols (tx*4, tx*4+1)
            ull b1 = bp[1];                // cols (tx*4+2, tx*4+3)
#pragma unroll
            for (int i = 0; i < 8; i++) {
                ull aa = *(const ull*)&As2[ty * 8 + i][k];
                FMA2(acc2[i][0], aa, b0);
                FMA2(acc2[i][1], aa, b1);
            }
        }
        __syncthreads();
    }

    // epilogue: store h + fused scores (row dot a_l / a_r across the 32 tx lanes)
    float al[4], ar[4];
#pragma unroll
    for (int j = 0; j < 4; j++) { al[j] = __ldg(a_l + tx * 4 + j); ar[j] = __ldg(a_r + tx * 4 + j); }

#pragma unroll
    for (int i = 0; i < 8; i++) {
        int gr = rowBase + ty * 8 + i;
        float2 p0 = *(float2*)&acc2[i][0];
        float2 p1 = *(float2*)&acc2[i][1];
        float pl = p0.x * al[0] + p0.y * al[1] + p1.x * al[2] + p1.y * al[3];
        float pr = p0.x * ar[0] + p0.y * ar[1] + p1.x * ar[2] + p1.y * ar[3];
        pl = warpSum(pl);
        pr = warpSum(pr);
        if (gr < n) {
            *(float4*)(g_h + (size_t)gr * F_OUT + tx * 4) =
                make_float4(p0.x, p0.y, p1.x, p1.y);
            if (tx == 0) { g_sl[gr] = pl; g_sr[gr] = pr; }
        }
    }
}

// ---------------- 2) CSR build ----------------
__global__ void zero_deg_kernel(int n) {
    int i = blockIdx.x * blockDim.x + threadIdx.x;
    if (i < n) g_deg[i] = 0;
}
__global__ void hist_kernel(const void* __restrict__ eidx, int e) {
    int i = blockIdx.x * blockDim.x + threadIdx.x;
    if (i < e) atomicAdd(&g_deg[edge_at(eidx, i)], 1);
}
__global__ __launch_bounds__(1024) void scan_kernel(int n) {
    __shared__ int sh_warp[32];
    __shared__ int sh_total;
    const int tid  = threadIdx.x;
    const int lane = tid & 31;
    const int wid  = tid >> 5;
    int running = 0;
    for (int base = 0; base < n; base += 1024) {
        int i = base + tid;
        int v = (i < n) ? g_deg[i] : 0;
        int incl = v;
#pragma unroll
        for (int o = 1; o < 32; o <<= 1) {
            int t = __shfl_up_sync(0xffffffffu, incl, o);
            if (lane >= o) incl += t;
        }
        if (lane == 31) sh_warp[wid] = incl;
        __syncthreads();
        if (tid < 32) {
            int ws = sh_warp[tid];
            int wi = ws;
#pragma unroll
            for (int o = 1; o < 32; o <<= 1) {
                int t = __shfl_up_sync(0xffffffffu, wi, o);
                if (tid >= o) wi += t;
            }
            sh_warp[tid] = wi - ws;   // exclusive warp offset
        }
        __syncthreads();
        int excl = incl - v + sh_warp[wid];
        if (i < n) { g_off[i] = running + excl; g_cur[i] = running + excl; }
        if (tid == 1023) sh_total = excl + v;
        __syncthreads();
        running += sh_total;
        __syncthreads();
    }
    if (tid == 0) g_off[n] = running;
}
__global__ void fill_kernel(const void* __restrict__ eidx, int e) {
    int i = blockIdx.x * blockDim.x + threadIdx.x;
    if (i < e) {
        int r = edge_at(eidx, i);
        int c = edge_at(eidx, (long long)e + i);
        int p = atomicAdd(&g_cur[r], 1);
        g_src[p] = c;
    }
}

// ---------------- 3) fused softmax + SpMM + bias + gated encoder ----------------
// One warp per destination node. TWO passes: online (max,sum) with NaN-safe merge,
// then weighted accumulation.
__global__ __launch_bounds__(256) void aggregate_kernel(
    const float* __restrict__ bias, const float* __restrict__ fc,
    const float* __restrict__ bf, float* __restrict__ out, int n)
{
    const int node = (blockIdx.x * blockDim.x + threadIdx.x) >> 5;
    const int lane = threadIdx.x & 31;
    if (node >= n) return;

    const int s = g_off[node];
    const int e = g_off[node + 1];
    const float sl = g_sl[node];

    // pass 1: online per-lane (max, sum-of-exp)
    float m = -INFINITY, sum = 0.f;
    for (int j = s + lane; j < e; j += 32) {
        int c = g_src[j];
        float v = sl + g_sr[c];
        v = v > 0.f ? v : ALPHA * v;
        if (v > m) { sum = sum * __expf(m - v) + 1.f; m = v; }
        else       { sum += __expf(v - m); }
    }
    // cross-lane merge. NaN-guard: when m == mn (incl. both -inf) weight is exactly 1,
    // avoiding exp(-inf - -inf) = exp(NaN).
#pragma unroll
    for (int o = 16; o > 0; o >>= 1) {
        float m2 = __shfl_xor_sync(0xffffffffu, m, o);
        float s2 = __shfl_xor_sync(0xffffffffu, sum, o);
        float mn = fmaxf(m, m2);
        float w1 = (m  == mn) ? 1.f : __expf(m  - mn);
        float w2 = (m2 == mn) ? 1.f : __expf(m2 - mn);
        sum = sum * w1 + s2 * w2;
        m = mn;
    }
    const float inv = 1.f / (sum + 1e-16f);

    // pass 2: weighted accumulation of h[src] rows (lane owns 4 features)
    float4 acc = make_float4(0.f, 0.f, 0.f, 0.f);
    for (int j0 = s; j0 < e; j0 += 32) {
        int   j = j0 + lane;
        int   c = 0;
        float w = 0.f;
        if (j < e) {
            c = g_src[j];
            float v = sl + g_sr[c];
            v = v > 0.f ? v : ALPHA * v;
            w = __expf(v - m) * inv;
        }
        int cnt = min(32, e - j0);
        for (int t = 0; t < cnt; t++) {
            int   cc = __shfl_sync(0xffffffffu, c, t);
            float ww = __shfl_sync(0xffffffffu, w, t);
            const float4 hv = *(const float4*)(g_h + (size_t)cc * F_OUT + lane * 4);
            acc.x += ww * hv.x;
            acc.y += ww * hv.y;
            acc.z += ww * hv.z;
            acc.w += ww * hv.w;
        }
    }

    // epilogue: + bias, sigmoid gate, relu(v) + gate*min(v,0)
    float4 bsv = *(const float4*)(bias + lane * 4);
    float4 v = make_float4(acc.x + bsv.x, acc.y + bsv.y, acc.z + bsv.z, acc.w + bsv.w);
    float4 fv = *(const float4*)(fc + lane * 4);
    float p = v.x * fv.x + v.y * fv.y + v.z * fv.z + v.w * fv.w;
    p = warpSum(p) + bf[0];
    float gate = 1.f / (1.f + __expf(-p));

    float4 o;
    o.x = (v.x < 0.f ? 0.f : v.x) + gate * (v.x > 0.f ? 0.f : v.x);
    o.y = (v.y < 0.f ? 0.f : v.y) + gate * (v.y > 0.f ? 0.f : v.y);
    o.z = (v.z < 0.f ? 0.f : v.z) + gate * (v.z > 0.f ? 0.f : v.z);
    o.w = (v.w < 0.f ? 0.f : v.w) + gate * (v.w > 0.f ? 0.f : v.w);
    *(float4*)(out + (size_t)node * F_OUT + lane * 4) = o;
}

// ---------------- launch ----------------
// NOTE: gemm_kernel is deliberately the 4th launch — ncu's -s/-c window captures
// the 4th launch in this harness, and the GEMM is the kernel we need profiled.
extern "C" void kernel_launch(void* const* d_in, const int* in_sizes, int n_in,
                              void* d_out, int out_size)
{
    const float* x      = (const float*)d_in[0];
    const void*  eidx   = d_in[1];               // [2, E]; int32 or int64 (detected)
    // d_in[2] = edge_attr (unused by the reference)
    const float* weight = (const float*)d_in[3];
    const float* bias   = (const float*)d_in[4];
    const float* a_l    = (const float*)d_in[5];
    const float* a_r    = (const float*)d_in[6];
    const float* fc     = (const float*)d_in[7];
    const float* bf     = (const float*)d_in[8];
    float*       out    = (float*)d_out;

    const int n = in_sizes[0] / F_IN;    // 100000
    const int e = in_sizes[1] / 2;       // 1600000

    detect_kernel<<<1, 32>>>((const int*)eidx);                 // 1
    zero_deg_kernel<<<(n + 255) / 256, 256>>>(n);               // 2
    hist_kernel<<<(e + 255) / 256, 256>>>(eidx, e);             // 3
    gemm_kernel<<<(n + 63) / 64, 256>>>(x, weight, a_l, a_r, n);// 4  <- profiled
    scan_kernel<<<1, 1024>>>(n);                                // 5
    fill_kernel<<<(e + 255) / 256, 256>>>(eidx, e);             // 6
    aggregate_kernel<<<(n + 7) / 8, 256>>>(bias, fc, bf, out, n); // 7
}

// round 15
// speedup vs baseline: 1.0974x; 1.0974x over previous
#include <cuda_runtime.h>
#include <math.h>
#include <stdint.h>

// Problem constants (fixed shapes per reference)
#define N_NODES 100000
#define N_EDGES 1600000
#define F_IN    256
#define F_OUT   128
#define ALPHA   0.2f

typedef unsigned long long ull;

// ---------------- device scratch (static; no allocation allowed) ----------------
__device__ __align__(16) float g_h[(size_t)N_NODES * F_OUT];   // 51.2 MB: h = x @ W
__device__ float g_sl[N_NODES];
__device__ float g_sr[N_NODES];
__device__ int   g_deg[N_NODES];
__device__ int   g_off[N_NODES + 1];
__device__ int   g_cur[N_NODES];
__device__ int   g_src[N_EDGES];
__device__ int   g_is64;

// ---------------- warp reduction helpers ----------------
__device__ __forceinline__ float warpSum(float v) {
#pragma unroll
    for (int o = 16; o > 0; o >>= 1) v += __shfl_xor_sync(0xffffffffu, v, o);
    return v;
}

// packed dual-fp32 FMA (PTX 8.6, sm_100+): acc = a*b + acc, lanewise on 2 floats
#define FMA2(acc, a, b) \
    asm volatile("fma.rn.f32x2 %0, %1, %2, %0;" : "+l"(acc) : "l"(a), "l"(b))
// duplicate one fp32 into both halves of a 64-bit register pair
#define DUP2(out, f) \
    asm volatile("mov.b64 %0, {%1, %1};" : "=l"(out) : "r"(__float_as_uint(f)))

// ---------------- 0) edge dtype detection ----------------
// int64 little-endian with values < 2^31 has zero hi-words at odd int32 slots.
__global__ void detect_kernel(const int* __restrict__ p) {
    int lane = threadIdx.x;
    int bad = 0;
    for (int k = lane; k < 256; k += 32)
        if (p[2 * k + 1] != 0) bad = 1;
    unsigned b = __ballot_sync(0xffffffffu, bad);
    if (lane == 0) g_is64 = (b == 0) ? 1 : 0;
}
__device__ __forceinline__ int edge_at(const void* eidx, long long elem) {
    if (g_is64) return (int)((const long long*)eidx)[elem];
    return ((const int*)eidx)[elem];
}

// ---------------- 1) f32x2 register-blocked GEMM: h = x @ W (+ fused scores) ----------
// CTA tile 128x128, 16x16 threads, 8x8 outputs per thread (rows ty*4 & 64+ty*4,
// cols tx*4 & 64+tx*4). A staged TRANSPOSED As[k][row] -> per k: 4 LDS.128 + 32 FMA2.
#define KC     32
#define APITCH 132     // floats; 528B row = 33*16 (LDS.128-aligned), bank-spread
#define BPITCH 132
__global__ __launch_bounds__(256) void gemm_kernel(
    const float* __restrict__ x, const float* __restrict__ w,
    const float* __restrict__ a_l, const float* __restrict__ a_r, int n)
{
    __shared__ __align__(16) float As[KC][APITCH];   // [k][row]
    __shared__ __align__(16) float Bs[KC][BPITCH];   // [k][col]

    const int tid = threadIdx.x;
    const int tx  = tid & 15;
    const int ty  = tid >> 4;
    const int rowBase = blockIdx.x * 128;

    ull acc2[8][4];
#pragma unroll
    for (int i = 0; i < 8; i++)
#pragma unroll
        for (int j = 0; j < 4; j++) acc2[i][j] = 0ull;

    for (int k0 = 0; k0 < F_IN; k0 += KC) {
        // stage A transposed: 128 rows x KC = 1024 float4 reads, 4/thread
#pragma unroll
        for (int l = 0; l < 4; l++) {
            int idx = tid + l * 256;       // 0..1023
            int r   = idx >> 3;            // row 0..127
            int q   = idx & 7;             // k-quad 0..7
            float4 v = make_float4(0.f, 0.f, 0.f, 0.f);
            int gr = rowBase + r;
            if (gr < n)
                v = *(const float4*)(x + (size_t)gr * F_IN + k0 + q * 4);
            As[q * 4 + 0][r] = v.x;
            As[q * 4 + 1][r] = v.y;
            As[q * 4 + 2][r] = v.z;
            As[q * 4 + 3][r] = v.w;
        }
        // stage B: KC x 128 = 1024 float4 reads, 4/thread (STS.128, conflict-free)
#pragma unroll
        for (int l = 0; l < 4; l++) {
            int idx = tid + l * 256;
            int r   = idx >> 5;            // k row 0..31
            int c4  = idx & 31;            // col quad
            *(float4*)&Bs[r][c4 * 4] =
                *(const float4*)(w + (size_t)(k0 + r) * F_OUT + c4 * 4);
        }
        __syncthreads();

#pragma unroll 8
        for (int k = 0; k < KC; k++) {
            // A: 8 row values via 2 LDS.128 (broadcast: 2 distinct addrs/warp)
            float4 a0 = *(const float4*)&As[k][ty * 4];
            float4 a1 = *(const float4*)&As[k][64 + ty * 4];
            // B: 8 col values via 2 LDS.128, used directly as 4 f32x2 pairs
            ull b[4];
            *(uint4*)&b[0] = *(const uint4*)&Bs[k][tx * 4];
            *(uint4*)&b[2] = *(const uint4*)&Bs[k][64 + tx * 4];
            // duplicate A values into register pairs
            ull a[8];
            DUP2(a[0], a0.x); DUP2(a[1], a0.y); DUP2(a[2], a0.z); DUP2(a[3], a0.w);
            DUP2(a[4], a1.x); DUP2(a[5], a1.y); DUP2(a[6], a1.z); DUP2(a[7], a1.w);
#pragma unroll
            for (int i = 0; i < 8; i++)
#pragma unroll
                for (int j = 0; j < 4; j++)
                    FMA2(acc2[i][j], a[i], b[j]);
        }
        __syncthreads();
    }

    // ---- epilogue: store h + fused scores (dot a_l/a_r, reduce over 16 tx lanes) ----
    float alv[8], arv[8];
#pragma unroll
    for (int jj = 0; jj < 4; jj++) {
        alv[jj]     = __ldg(a_l + tx * 4 + jj);
        alv[4 + jj] = __ldg(a_l + 64 + tx * 4 + jj);
        arv[jj]     = __ldg(a_r + tx * 4 + jj);
        arv[4 + jj] = __ldg(a_r + 64 + tx * 4 + jj);
    }
#pragma unroll
    for (int i = 0; i < 8; i++) {
        const int lr = (i < 4) ? (ty * 4 + i) : (64 + ty * 4 + (i - 4));
        const int gr = rowBase + lr;
        float2 c0 = *(float2*)&acc2[i][0];
        float2 c1 = *(float2*)&acc2[i][1];
        float2 c2 = *(float2*)&acc2[i][2];
        float2 c3 = *(float2*)&acc2[i][3];
        float pl = c0.x * alv[0] + c0.y * alv[1] + c1.x * alv[2] + c1.y * alv[3]
                 + c2.x * alv[4] + c2.y * alv[5] + c3.x * alv[6] + c3.y * alv[7];
        float pr = c0.x * arv[0] + c0.y * arv[1] + c1.x * arv[2] + c1.y * arv[3]
                 + c2.x * arv[4] + c2.y * arv[5] + c3.x * arv[6] + c3.y * arv[7];
#pragma unroll
        for (int o = 1; o < 16; o <<= 1) {          // reduce across the 16 tx lanes
            pl += __shfl_xor_sync(0xffffffffu, pl, o);
            pr += __shfl_xor_sync(0xffffffffu, pr, o);
        }
        if (gr < n) {
            *(float4*)(g_h + (size_t)gr * F_OUT + tx * 4) =
                make_float4(c0.x, c0.y, c1.x, c1.y);
            *(float4*)(g_h + (size_t)gr * F_OUT + 64 + tx * 4) =
                make_float4(c2.x, c2.y, c3.x, c3.y);
            if (tx == 0) { g_sl[gr] = pl; g_sr[gr] = pr; }
        }
    }
}

// ---------------- 2) CSR build ----------------
__global__ void zero_deg_kernel(int n) {
    int i = blockIdx.x * blockDim.x + threadIdx.x;
    if (i < n) g_deg[i] = 0;
}
__global__ void hist_kernel(const void* __restrict__ eidx, int e) {
    int i = blockIdx.x * blockDim.x + threadIdx.x;
    if (i < e) atomicAdd(&g_deg[edge_at(eidx, i)], 1);
}
__global__ __launch_bounds__(1024) void scan_kernel(int n) {
    __shared__ int sh_warp[32];
    __shared__ int sh_total;
    const int tid  = threadIdx.x;
    const int lane = tid & 31;
    const int wid  = tid >> 5;
    int running = 0;
    for (int base = 0; base < n; base += 1024) {
        int i = base + tid;
        int v = (i < n) ? g_deg[i] : 0;
        int incl = v;
#pragma unroll
        for (int o = 1; o < 32; o <<= 1) {
            int t = __shfl_up_sync(0xffffffffu, incl, o);
            if (lane >= o) incl += t;
        }
        if (lane == 31) sh_warp[wid] = incl;
        __syncthreads();
        if (tid < 32) {
            int ws = sh_warp[tid];
            int wi = ws;
#pragma unroll
            for (int o = 1; o < 32; o <<= 1) {
                int t = __shfl_up_sync(0xffffffffu, wi, o);
                if (tid >= o) wi += t;
            }
            sh_warp[tid] = wi - ws;   // exclusive warp offset
        }
        __syncthreads();
        int excl = incl - v + sh_warp[wid];
        if (i < n) { g_off[i] = running + excl; g_cur[i] = running + excl; }
        if (tid == 1023) sh_total = excl + v;
        __syncthreads();
        running += sh_total;
        __syncthreads();
    }
    if (tid == 0) g_off[n] = running;
}
__global__ void fill_kernel(const void* __restrict__ eidx, int e) {
    int i = blockIdx.x * blockDim.x + threadIdx.x;
    if (i < e) {
        int r = edge_at(eidx, i);
        int c = edge_at(eidx, (long long)e + i);
        int p = atomicAdd(&g_cur[r], 1);
        g_src[p] = c;
    }
}

// ---------------- 3) fused softmax + SpMM + bias + gated encoder ----------------
// One warp per destination node. TWO passes: online (max,sum) with NaN-safe merge,
// then weighted accumulation.
__global__ __launch_bounds__(256) void aggregate_kernel(
    const float* __restrict__ bias, const float* __restrict__ fc,
    const float* __restrict__ bf, float* __restrict__ out, int n)
{
    const int node = (blockIdx.x * blockDim.x + threadIdx.x) >> 5;
    const int lane = threadIdx.x & 31;
    if (node >= n) return;

    const int s = g_off[node];
    const int e = g_off[node + 1];
    const float sl = g_sl[node];

    // pass 1: online per-lane (max, sum-of-exp)
    float m = -INFINITY, sum = 0.f;
    for (int j = s + lane; j < e; j += 32) {
        int c = g_src[j];
        float v = sl + g_sr[c];
        v = v > 0.f ? v : ALPHA * v;
        if (v > m) { sum = sum * __expf(m - v) + 1.f; m = v; }
        else       { sum += __expf(v - m); }
    }
    // cross-lane merge. NaN-guard: when m == mn (incl. both -inf) weight is exactly 1,
    // avoiding exp(-inf - -inf) = exp(NaN).
#pragma unroll
    for (int o = 16; o > 0; o >>= 1) {
        float m2 = __shfl_xor_sync(0xffffffffu, m, o);
        float s2 = __shfl_xor_sync(0xffffffffu, sum, o);
        float mn = fmaxf(m, m2);
        float w1 = (m  == mn) ? 1.f : __expf(m  - mn);
        float w2 = (m2 == mn) ? 1.f : __expf(m2 - mn);
        sum = sum * w1 + s2 * w2;
        m = mn;
    }
    const float inv = 1.f / (sum + 1e-16f);

    // pass 2: weighted accumulation of h[src] rows (lane owns 4 features)
    float4 acc = make_float4(0.f, 0.f, 0.f, 0.f);
    for (int j0 = s; j0 < e; j0 += 32) {
        int   j = j0 + lane;
        int   c = 0;
        float w = 0.f;
        if (j < e) {
            c = g_src[j];
            float v = sl + g_sr[c];
            v = v > 0.f ? v : ALPHA * v;
            w = __expf(v - m) * inv;
        }
        int cnt = min(32, e - j0);
        for (int t = 0; t < cnt; t++) {
            int   cc = __shfl_sync(0xffffffffu, c, t);
            float ww = __shfl_sync(0xffffffffu, w, t);
            const float4 hv = *(const float4*)(g_h + (size_t)cc * F_OUT + lane * 4);
            acc.x += ww * hv.x;
            acc.y += ww * hv.y;
            acc.z += ww * hv.z;
            acc.w += ww * hv.w;
        }
    }

    // epilogue: + bias, sigmoid gate, relu(v) + gate*min(v,0)
    float4 bsv = *(const float4*)(bias + lane * 4);
    float4 v = make_float4(acc.x + bsv.x, acc.y + bsv.y, acc.z + bsv.z, acc.w + bsv.w);
    float4 fv = *(const float4*)(fc + lane * 4);
    float p = v.x * fv.x + v.y * fv.y + v.z * fv.z + v.w * fv.w;
    p = warpSum(p) + bf[0];
    float gate = 1.f / (1.f + __expf(-p));

    float4 o;
    o.x = (v.x < 0.f ? 0.f : v.x) + gate * (v.x > 0.f ? 0.f : v.x);
    o.y = (v.y < 0.f ? 0.f : v.y) + gate * (v.y > 0.f ? 0.f : v.y);
    o.z = (v.z < 0.f ? 0.f : v.z) + gate * (v.z > 0.f ? 0.f : v.z);
    o.w = (v.w < 0.f ? 0.f : v.w) + gate * (v.w > 0.f ? 0.f : v.w);
    *(float4*)(out + (size_t)node * F_OUT + lane * 4) = o;
}

// ---------------- launch ----------------
// NOTE: gemm_kernel is deliberately the 4th launch — ncu's -s/-c window captures
// the 4th launch in this harness, and the GEMM is the kernel we need profiled.
extern "C" void kernel_launch(void* const* d_in, const int* in_sizes, int n_in,
                              void* d_out, int out_size)
{
    const float* x      = (const float*)d_in[0];
    const void*  eidx   = d_in[1];               // [2, E]; int32 or int64 (detected)
    // d_in[2] = edge_attr (unused by the reference)
    const float* weight = (const float*)d_in[3];
    const float* bias   = (const float*)d_in[4];
    const float* a_l    = (const float*)d_in[5];
    const float* a_r    = (const float*)d_in[6];
    const float* fc     = (const float*)d_in[7];
    const float* bf     = (const float*)d_in[8];
    float*       out    = (float*)d_out;

    const int n = in_sizes[0] / F_IN;    // 100000
    const int e = in_sizes[1] / 2;       // 1600000

    detect_kernel<<<1, 32>>>((const int*)eidx);                   // 1
    zero_deg_kernel<<<(n + 255) / 256, 256>>>(n);                 // 2
    hist_kernel<<<(e + 255) / 256, 256>>>(eidx, e);               // 3
    gemm_kernel<<<(n + 127) / 128, 256>>>(x, weight, a_l, a_r, n);// 4  <- profiled
    scan_kernel<<<1, 1024>>>(n);                                  // 5
    fill_kernel<<<(e + 255) / 256, 256>>>(eidx, e);               // 6
    aggregate_kernel<<<(n + 7) / 8, 256>>>(bias, fc, bf, out, n); // 7
}